// round 16
// baseline (speedup 1.0000x reference)
#include <cuda_runtime.h>
#include <cuda_fp16.h>
#include <cstdint>
#include <math.h>

#define Bb 32
#define Hh 1024
#define Ss 512
#define Tt 32
#define N3 3072
#define NN 6144
#define NGEMM 128        // 64 h-slices x 2 batch-halves
#define NSCOR 16         // 2 batches each
#define GRID 144
#define THREADS 384

// smem layout (GEMM CTAs)
#define SM_B 0            // 32768: B stage (own batch-half, compacted)
#define SM_Y 32768        // 12288: y [kq 4][48][16] f32
#define SM_GX 45056       // 3072: cached gi [48][16]
#define SM_HOLD 48128     // 1024: hold h [16][16]
#define SM_BIAS 49152     // 320: br,bz,bni,bnh,v1 x16
#define SM_C256 49472     // 1024: [256] c elements
#define SM_FLG 50496      // 16
#define DSMEM 50688

// ===================== helpers =====================
__device__ __forceinline__ uint32_t smem_u32(const void* p) {
    uint32_t a;
    asm("{ .reg .u64 t; cvta.to.shared.u64 t, %1; cvt.u32.u64 %0, t; }" : "=r"(a) : "l"(p));
    return a;
}
__device__ __forceinline__ uint32_t pack_h2(__half x, __half y) {
    return (uint32_t)__half_as_ushort(x) | ((uint32_t)__half_as_ushort(y) << 16);
}
__device__ __forceinline__ float fsigmoid(float x) { return 1.f / (1.f + __expf(-x)); }
__device__ __forceinline__ float ftanh(float x) { return 2.f / (1.f + __expf(-2.f * x)) - 1.f; }
__device__ __forceinline__ void mma16816(float* c, const uint32_t* a, uint32_t b0, uint32_t b1) {
    asm volatile(
        "mma.sync.aligned.m16n8k16.row.col.f32.f16.f16.f32 "
        "{%0,%1,%2,%3}, {%4,%5,%6,%7}, {%8,%9}, {%0,%1,%2,%3};"
        : "+f"(c[0]), "+f"(c[1]), "+f"(c[2]), "+f"(c[3])
        : "r"(a[0]), "r"(a[1]), "r"(a[2]), "r"(a[3]), "r"(b0), "r"(b1));
}
// B-fragment byte offset for (k=j in [0,1024), n=b in [0,32))
__device__ __forceinline__ uint32_t bx_off(int j, int b) {
    int kc = j >> 4, r = j & 15;
    int nn = b >> 3, g = b & 7, t = (r & 7) >> 1;
    return (uint32_t)(kc * 1024 + nn * 256 + (g * 4 + t) * 8 + ((r >= 8) ? 4 : 0) + (r & 1) * 2);
}
__device__ __forceinline__ unsigned atom_add_acqrel(unsigned* p, unsigned v) {
    unsigned old;
    asm volatile("atom.add.acq_rel.gpu.u32 %0, [%1], %2;" : "=r"(old) : "l"(p), "r"(v) : "memory");
    return old;
}
__device__ __forceinline__ unsigned ld_acquire(unsigned* p) {
    unsigned v;
    asm volatile("ld.acquire.gpu.u32 %0, [%1];" : "=r"(v) : "l"(p) : "memory");
    return v;
}
__device__ __forceinline__ void st_release(unsigned* p, unsigned v) {
    asm volatile("st.release.gpu.u32 [%0], %1;" :: "l"(p), "r"(v) : "memory");
}

// ===================== device scratch =====================
// A fragments: [m 64][wid 12][p 16][lane 32] uint4 (warp wid = gate*4 + kq)
__device__ __align__(128) uint4 g_axh[393216];   // w_ih fp16 hi
__device__ __align__(128) uint4 g_axl[393216];   // w_ih fp16 lo (x4096)
__device__ __align__(128) uint4 g_ahh[393216];   // w_hh fp16 hi
__device__ __align__(128) char g_bx[2][65536];   // B frags fp16 [x|h]
__device__ __align__(16) float g_cp[Tt * 64 * Bb]; // c partials [t][m][b]
__device__ __align__(16) float g_vp[2][8][Hh];
__device__ __align__(16) float g_v1[Hh];
__device__ __align__(16) float g_v2[Hh];
__device__ __align__(16) float g_bias[NN];
__device__ int g_mask_nzv[Bb];
__device__ unsigned g_hcnt, g_xcnt;
__device__ unsigned g_hrel, g_xrel;

// ===================== prep kernels =====================
__global__ void prep_pack_b(const float* __restrict__ features,
                            const float* __restrict__ b_ih,
                            const float* __restrict__ b_hh,
                            const float* __restrict__ mask) {
    int b = blockIdx.x, tid = threadIdx.x;
    int lane = tid & 31, wid = tid >> 5;
    if (b == 0 && tid == 0) { g_hcnt = 0u; g_xcnt = 0u; g_hrel = 0u; g_xrel = 0u; }
    int bi = b * 256 + tid;
    if (bi < N3) g_bias[bi] = b_ih[bi];
    else if (bi < NN) g_bias[bi] = b_hh[bi - N3];
    __shared__ unsigned wnz[8];
    float m0 = mask[b * Ss + tid], m1 = mask[b * Ss + tid + 256];
    unsigned bal = __ballot_sync(0xFFFFFFFFu, (m0 != 0.f) || (m1 != 0.f));
    if (lane == 0) wnz[wid] = bal;
    __syncthreads();
    if (tid == 0) {
        unsigned o = 0;
#pragma unroll
        for (int i = 0; i < 8; i++) o |= wnz[i];
        g_mask_nzv[b] = (o != 0u);
    }
#pragma unroll
    for (int jj = 0; jj < 4; jj++) {
        int j = tid + jj * 256;
        float v = features[b * Hh + j];
        uint32_t off = bx_off(j, b);
        *(unsigned short*)(g_bx[0] + off) = __half_as_ushort(__float2half_rn(v));
        *(unsigned short*)(g_bx[1] + off) = 0;
    }
}

__global__ void prep_v(const float* __restrict__ W1, const float* __restrict__ W2,
                       const float* __restrict__ V) {
    int hc = blockIdx.x, sel = blockIdx.y, tid = threadIdx.x;
    const float* W = sel ? W2 : W1;
    __shared__ float vs[128];
    if (tid < 128) vs[tid] = V[hc * 128 + tid];
    __syncthreads();
    float acc[4] = {0.f, 0.f, 0.f, 0.f};
    for (int h = 0; h < 128; h++) {
        const float* row = W + (size_t)(hc * 128 + h) * Hh;
        float vh = vs[h];
#pragma unroll
        for (int q = 0; q < 4; q++) acc[q] = fmaf(vh, row[tid + q * 256], acc[q]);
    }
#pragma unroll
    for (int q = 0; q < 4; q++) g_vp[sel][hc][tid + q * 256] = acc[q];
}

__global__ void prep_vred() {
    int i = blockIdx.x * 256 + threadIdx.x;
    int sel = i >> 10, d = i & 1023;
    float s = 0.f;
#pragma unroll
    for (int hc = 0; hc < 8; hc++) s += g_vp[sel][hc][d];
    if (sel) g_v2[d] = s; else g_v1[d] = s;
}

// pack W rows: slice m, warp (wm,kq) -> gate wm, rows m*16+jl, K-quarter kq
__global__ void prep_wfr(const float* __restrict__ w_ih, const float* __restrict__ w_hh) {
    int idx = blockIdx.x * 256 + threadIdx.x;   // 393216
    int lane = idx & 31;
    int p = (idx >> 5) & 15;
    int rest = idx >> 9;                         // 0..767
    int wid = rest % 12;
    int m = rest / 12;
    int wm = wid >> 2, kq = wid & 3;
    int gq = lane >> 2, tq = lane & 3;
    int k0 = kq * 256 + p * 16 + 2 * tq;

    int jl[2] = {gq, gq + 8};
    float vx[8], vh4[8];
#pragma unroll
    for (int rr = 0; rr < 2; rr++) {
        int Wrow = wm * 1024 + m * 16 + jl[rr];
        const float* Xr = w_ih + (size_t)Wrow * Hh;
        const float* Hr = w_hh + (size_t)Wrow * Hh;
        vx[rr * 2 + 0] = Xr[k0];     vx[rr * 2 + 1] = Xr[k0 + 1];
        vx[rr * 2 + 4] = Xr[k0 + 8]; vx[rr * 2 + 5] = Xr[k0 + 9];
        vh4[rr * 2 + 0] = Hr[k0];     vh4[rr * 2 + 1] = Hr[k0 + 1];
        vh4[rr * 2 + 4] = Hr[k0 + 8]; vh4[rr * 2 + 5] = Hr[k0 + 9];
    }
    uint32_t xh[4], xl[4], hh[4];
#pragma unroll
    for (int i = 0; i < 4; i++) {
        float a = vx[2 * i], b = vx[2 * i + 1];
        __half ha = __float2half_rn(a), hb = __float2half_rn(b);
        __half la = __float2half_rn((a - __half2float(ha)) * 4096.f);
        __half lb = __float2half_rn((b - __half2float(hb)) * 4096.f);
        xh[i] = pack_h2(ha, hb);
        xl[i] = pack_h2(la, lb);
        hh[i] = pack_h2(__float2half_rn(vh4[2 * i]), __float2half_rn(vh4[2 * i + 1]));
    }
    g_axh[idx] = make_uint4(xh[0], xh[1], xh[2], xh[3]);
    g_axl[idx] = make_uint4(xl[0], xl[1], xl[2], xl[3]);
    g_ahh[idx] = make_uint4(hh[0], hh[1], hh[2], hh[3]);
}

// ===================== persistent kernel =====================
extern __shared__ char dsm[];

// stage own batch-half columns (32KB compacted: 64 kc x 512B)
__device__ __forceinline__ void stageB(const char* __restrict__ src, int bh, int tid) {
    uint32_t sb = smem_u32(dsm);
    for (int i = tid; i < 2048; i += THREADS) {
        int kc = i >> 5, ch = i & 31;
        asm volatile("cp.async.cg.shared.global [%0], [%1], 16;"
            :: "r"(sb + i * 16),
               "l"(__cvta_generic_to_global(src + kc * 1024 + bh * 512 + ch * 16)) : "memory");
    }
    asm volatile("cp.async.commit_group;" ::: "memory");
    asm volatile("cp.async.wait_group 0;" ::: "memory");
    __syncthreads();
}

__global__ void __launch_bounds__(THREADS, 1)
gru_persist(const float* __restrict__ inputs, const float* __restrict__ mask,
            float* __restrict__ probs, float* __restrict__ ctx) {
    const int c = blockIdx.x;            // 0..143
    const int tid = threadIdx.x;
    const int wid = tid >> 5;
    const int lane = tid & 31;

    // ================= scorer CTAs (2 batches each) =================
    if (c >= NGEMM) {
        const int pb = (c - NGEMM) * 2;  // first batch of the pair
        float* sa  = (float*)dsm;               // [2][512]
        float* v2s = (float*)(dsm + 4096);
        float* p   = (float*)(dsm + 8192);      // 512 f
        float* red2 = (float*)(dsm + 10240);
        int*   si2  = (int*)(dsm + 10496);
        int*   sfl  = (int*)(dsm + 10752);

        if (tid == 0) {
            int nz = 0;
#pragma unroll
            for (int i = 0; i < Bb; i++) nz |= g_mask_nzv[i];
            sfl[0] = nz;
        }
        for (int i = tid; i < Hh; i += THREADS) v2s[i] = g_v2[i];
        __syncthreads();
        const bool mask_nz = (sfl[0] != 0);

        // a for both batches
#pragma unroll
        for (int bi = 0; bi < 2; bi++) {
            int b2 = pb + bi;
            for (int row = wid; row < Ss; row += 12) {
                const float* r = inputs + ((size_t)b2 * Ss + row) * Hh;
                float acc = 0.f;
#pragma unroll
                for (int i = 0; i < 8; i++) {
                    float4 x4 = *(const float4*)&r[(i * 32 + lane) * 4];
                    float4 v4 = *(const float4*)&v2s[(i * 32 + lane) * 4];
                    acc += x4.x * v4.x + x4.y * v4.y + x4.z * v4.z + x4.w * v4.w;
                }
#pragma unroll
                for (int o = 16; o > 0; o >>= 1) acc += __shfl_xor_sync(0xFFFFFFFFu, acc, o);
                if (lane == 0) sa[bi * 512 + row] = acc;
            }
        }
        __syncthreads();

        for (int t = 0; t < Tt; t++) {
            if (tid == 0) { while (ld_acquire(&g_hrel) < (unsigned)(t + 1)) { } }
            __syncthreads();
            // c for both batches in parallel: tid<128
            if (tid < 128) {
                int bi = tid >> 6, idx = tid & 63;
                float v = g_cp[(t * 64 + idx) * Bb + pb + bi];
#pragma unroll
                for (int o = 16; o > 0; o >>= 1) v += __shfl_xor_sync(0xFFFFFFFFu, v, o);
                if (lane == 0) red2[wid] = v;
            }
            __syncthreads();
            const float cA = red2[0] + red2[1];
            const float cB = red2[2] + red2[3];
#pragma unroll
            for (int bi = 0; bi < 2; bi++) {
                const int b2 = pb + bi;
                const float c0v = bi ? cB : cA;
                float s0 = 0.f, s1 = 0.f;
                if (tid < 256) {
                    s0 = ftanh(c0v + sa[bi * 512 + tid]);
                    s1 = ftanh(c0v + sa[bi * 512 + tid + 256]);
                    float* pr = probs + ((size_t)b2 * Tt + t) * Ss;
                    pr[tid] = s0;
                    pr[tid + 256] = s1;
                }
                if (t == 0 || mask_nz) {
                    if (tid < 256) {
                        float m0 = s0 + mask[b2 * Ss + tid];
                        float m1 = s1 + mask[b2 * Ss + tid + 256];
                        float bv = m0; int bi2 = tid;
                        if (m1 > bv) { bv = m1; bi2 = tid + 256; }
#pragma unroll
                        for (int o = 16; o > 0; o >>= 1) {
                            float v = __shfl_xor_sync(0xFFFFFFFFu, bv, o);
                            int ii = __shfl_xor_sync(0xFFFFFFFFu, bi2, o);
                            if (v > bv || (v == bv && ii < bi2)) { bv = v; bi2 = ii; }
                        }
                        if (lane == 0) { red2[8 + wid] = bv; si2[wid] = bi2; }
                    }
                    __syncthreads();
                    if (tid == 0) {
                        float v = red2[8]; int ii = si2[0];
#pragma unroll
                        for (int i = 1; i < 8; i++) {
                            float v2 = red2[8 + i]; int i2 = si2[i];
                            if (v2 > v || (v2 == v && i2 < ii)) { v = v2; ii = i2; }
                        }
                        si2[15] = ii;
                    }
                    __syncthreads();
                    int idx = si2[15];
                    const float* xr = inputs + ((size_t)b2 * Ss + idx) * Hh;
                    for (int k2 = tid; k2 < Hh; k2 += THREADS) {
                        *(unsigned short*)(g_bx[0] + bx_off(k2, b2)) =
                            __half_as_ushort(__float2half_rn(xr[k2]));
                    }
                    __syncthreads();
                }
            }
            if (t == 0 || mask_nz) {
                if (tid == 0) {
                    unsigned prev = atom_add_acqrel(&g_xcnt, 1u);
                    if ((prev & 15u) == 15u) st_release(&g_xrel, (unsigned)(t + 1));
                }
            }
            if (t == 0) {
                // ctx for both batches (overlapped with remaining steps)
#pragma unroll
                for (int bi = 0; bi < 2; bi++) {
                    const int b2 = pb + bi;
                    for (int s = tid; s < Ss; s += THREADS)
                        p[s] = probs[(size_t)b2 * Tt * Ss + s] + mask[b2 * Ss + s];
                    __syncthreads();
                    if (tid < 256) {
                        float m = fmaxf(p[tid], p[tid + 256]);
#pragma unroll
                        for (int o = 16; o > 0; o >>= 1) m = fmaxf(m, __shfl_xor_sync(0xFFFFFFFFu, m, o));
                        if (lane == 0) red2[16 + wid] = m;
                    }
                    __syncthreads();
                    if (tid == 0) {
                        float mm = red2[16];
#pragma unroll
                        for (int i = 1; i < 8; i++) mm = fmaxf(mm, red2[16 + i]);
                        red2[24] = mm;
                    }
                    __syncthreads();
                    const float mx = red2[24];
                    float sm = 0.f;
                    if (tid < 256) {
                        float e0 = __expf(p[tid] - mx), e1 = __expf(p[tid + 256] - mx);
                        p[tid] = e0; p[tid + 256] = e1;
                        sm = e0 + e1;
#pragma unroll
                        for (int o = 16; o > 0; o >>= 1) sm += __shfl_xor_sync(0xFFFFFFFFu, sm, o);
                        if (lane == 0) red2[32 + wid] = sm;
                    }
                    __syncthreads();
                    if (tid == 0) {
                        float ss = 0.f;
#pragma unroll
                        for (int i = 0; i < 8; i++) ss += red2[32 + i];
                        red2[40] = ss;
                    }
                    __syncthreads();
                    const float Z = red2[40];
                    if (tid < 256) {
                        float acc[4] = {0.f, 0.f, 0.f, 0.f};
                        for (int s = 0; s < Ss; s++) {
                            const float* row = inputs + ((size_t)b2 * Ss + s) * Hh;
                            float ps = p[s];
#pragma unroll
                            for (int q = 0; q < 4; q++) acc[q] = fmaf(ps, row[tid + q * 256], acc[q]);
                        }
#pragma unroll
                        for (int q = 0; q < 4; q++) ctx[b2 * Hh + tid + q * 256] = acc[q] / Z;
                    }
                    __syncthreads();
                }
            }
        }
        return;
    }

    // ================= GEMM + fused-update CTAs =================
    const int m = c >> 1;                // h-slice 0..63
    const int bh = c & 1;                // batch half
    const int kq = wid & 3;              // K-quarter

    float* yq   = (float*)(dsm + SM_Y);          // [kq][48][16]
    float* gxs  = (float*)(dsm + SM_GX);         // [48][16]
    float* hold = (float*)(dsm + SM_HOLD);       // [16][16]
    float* brS  = (float*)(dsm + SM_BIAS);
    float* bzS  = brS + 16;
    float* bniS = brS + 32;
    float* bnhS = brS + 48;
    float* v1S  = brS + 64;
    float* c256 = (float*)(dsm + SM_C256);
    int*   sfl  = (int*)(dsm + SM_FLG);

    if (tid == 0) {
        int nz = 0;
#pragma unroll
        for (int i = 0; i < Bb; i++) nz |= g_mask_nzv[i];
        sfl[0] = nz;
    }
    if (tid < 16) {
        int jg = m * 16 + tid;
        brS[tid] = g_bias[jg] + g_bias[3072 + jg];
        bzS[tid] = g_bias[1024 + jg] + g_bias[4096 + jg];
        bniS[tid] = g_bias[2048 + jg];
        bnhS[tid] = g_bias[5120 + jg];
        v1S[tid] = g_v1[jg];
    }
    for (int i = tid; i < 256; i += THREADS) hold[i] = 0.f;
    __syncthreads();
    const bool mask_nz = (sfl[0] != 0);

    const size_t abase = ((size_t)(m * 12 + wid)) * 512;   // [m][wid][p][lane]
    const uint4* Axh = g_axh + abase;
    const uint4* Axl = g_axl + abase;
    const uint4* Ahh = g_ahh + abase;

    // ---- steady-state h-weights live in registers (loaded once) ----
    uint4 AHH[16];
#pragma unroll
    for (int p = 0; p < 16; p++) AHH[p] = Ahh[p * 32 + lane];

    float* ybW = yq + kq * 768;          // this K-quarter's buffer [48][16]
    const int wm = wid >> 2;
    const int r0 = wm * 16 + (lane >> 2);
    const int c0f = 2 * (lane & 3);

    for (int t = 0; t < Tt; t++) {
        const bool xp = (t <= 1) || mask_nz;
        const bool hp = (t >= 1);
        if (t >= 1) {
            if (tid == 0) {
                while (ld_acquire(&g_hrel) < (unsigned)t) { }
                if (xp) { while (ld_acquire(&g_xrel) < (unsigned)t) { } }
            }
            __syncthreads();
        }

        if (xp) {
            stageB(g_bx[0], bh, tid);
            float acch[2][4], accl[2][4];
#pragma unroll
            for (int i = 0; i < 2; i++)
#pragma unroll
                for (int j = 0; j < 4; j++) { acch[i][j] = 0.f; accl[i][j] = 0.f; }
            uint4 AH[4], AL[4];
#pragma unroll
            for (int p = 0; p < 3; p++) { AH[p] = Axh[p * 32 + lane]; AL[p] = Axl[p * 32 + lane]; }
#pragma unroll
            for (int p = 0; p < 16; p++) {
                const int s = p & 3;
                if (p + 3 < 16) {
                    const int q = (p + 3) & 3;
                    AH[q] = Axh[(p + 3) * 32 + lane];
                    AL[q] = Axl[(p + 3) * 32 + lane];
                }
                const char* bb = dsm + (kq * 16 + p) * 512 + lane * 8;
#pragma unroll
                for (int nn = 0; nn < 2; nn++) {
                    uint2 bv = *(const uint2*)(bb + nn * 256);
                    mma16816(acch[nn], &AH[s].x, bv.x, bv.y);
                    mma16816(accl[nn], &AL[s].x, bv.x, bv.y);
                }
            }
#pragma unroll
            for (int nn = 0; nn < 2; nn++) {
                int col = nn * 8 + c0f;
                ybW[r0 * 16 + col]           = acch[nn][0] + accl[nn][0] * (1.f / 4096.f);
                ybW[r0 * 16 + col + 1]       = acch[nn][1] + accl[nn][1] * (1.f / 4096.f);
                ybW[(r0 + 8) * 16 + col]     = acch[nn][2] + accl[nn][2] * (1.f / 4096.f);
                ybW[(r0 + 8) * 16 + col + 1] = acch[nn][3] + accl[nn][3] * (1.f / 4096.f);
            }
            __syncthreads();
            for (int i = tid; i < 768; i += THREADS)
                gxs[i] = yq[i] + yq[768 + i] + yq[1536 + i] + yq[2304 + i];
            __syncthreads();
        }

        if (hp) {
            stageB(g_bx[1], bh, tid);
            float acch[2][4];
#pragma unroll
            for (int i = 0; i < 2; i++)
#pragma unroll
                for (int j = 0; j < 4; j++) acch[i][j] = 0.f;
#pragma unroll
            for (int p = 0; p < 16; p++) {
                const char* bb = dsm + (kq * 16 + p) * 512 + lane * 8;
#pragma unroll
                for (int nn = 0; nn < 2; nn++) {
                    uint2 bv = *(const uint2*)(bb + nn * 256);
                    mma16816(acch[nn], &AHH[p].x, bv.x, bv.y);
                }
            }
#pragma unroll
            for (int nn = 0; nn < 2; nn++) {
                int col = nn * 8 + c0f;
                ybW[r0 * 16 + col]           = acch[nn][0];
                ybW[r0 * 16 + col + 1]       = acch[nn][1];
                ybW[(r0 + 8) * 16 + col]     = acch[nn][2];
                ybW[(r0 + 8) * 16 + col + 1] = acch[nn][3];
            }
            __syncthreads();
        }

        // ---- fused GRU update for h[m*16..+16) x batches[bh*16..+16) ----
        if (tid < 256) {
            int jl = tid >> 4, bl = tid & 15;
            float yr = 0.f, yz = 0.f, yn = 0.f;
            if (hp) {
                yr = yq[jl * 16 + bl]        + yq[768 + jl * 16 + bl]
                   + yq[1536 + jl * 16 + bl] + yq[2304 + jl * 16 + bl];
                yz = yq[(16 + jl) * 16 + bl]        + yq[768 + (16 + jl) * 16 + bl]
                   + yq[1536 + (16 + jl) * 16 + bl] + yq[2304 + (16 + jl) * 16 + bl];
                yn = yq[(32 + jl) * 16 + bl]        + yq[768 + (32 + jl) * 16 + bl]
                   + yq[1536 + (32 + jl) * 16 + bl] + yq[2304 + (32 + jl) * 16 + bl];
            }
            float r = fsigmoid(gxs[jl * 16 + bl] + yr + brS[jl]);
            float z = fsigmoid(gxs[(16 + jl) * 16 + bl] + yz + bzS[jl]);
            float nv = ftanh(gxs[(32 + jl) * 16 + bl] + bniS[jl] + r * (yn + bnhS[jl]));
            float hnew = (1.f - z) * nv + z * hold[tid];
            hold[tid] = hnew;
            *(unsigned short*)(g_bx[1] + bx_off(m * 16 + jl, bh * 16 + bl)) =
                __half_as_ushort(__float2half_rn(hnew));
            c256[tid] = v1S[jl] * hnew;
        }
        __syncthreads();
        if (tid < 16) {
            float s = 0.f;
#pragma unroll
            for (int jl = 0; jl < 16; jl++) s += c256[jl * 16 + tid];
            g_cp[(t * 64 + m) * Bb + bh * 16 + tid] = s;
        }
        __syncthreads();
        if (tid == 0) {
            unsigned prev = atom_add_acqrel(&g_hcnt, 1u);
            if ((prev & 127u) == 127u) st_release(&g_hrel, (unsigned)(t + 1));
        }
    }
}

// ===================== launch =====================
extern "C" void kernel_launch(void* const* d_in, const int* in_sizes, int n_in,
                              void* d_out, int out_size) {
    const float* inputs   = (const float*)d_in[0];
    const float* mask     = (const float*)d_in[1];
    // d_in[2] = inputs_embeds (unused, use_emb=False)
    const float* features = (const float*)d_in[3];
    const float* w_ih     = (const float*)d_in[4];
    const float* b_ih     = (const float*)d_in[5];
    const float* w_hh     = (const float*)d_in[6];
    const float* b_hh     = (const float*)d_in[7];
    const float* W1       = (const float*)d_in[8];
    const float* W2       = (const float*)d_in[9];
    const float* V        = (const float*)d_in[10];

    float* out   = (float*)d_out;
    float* probs = out;                            // [B, T, S]
    float* ctx   = out + (size_t)Bb * Tt * Ss;     // [B, H]

    cudaFuncSetAttribute(gru_persist, cudaFuncAttributeMaxDynamicSharedMemorySize, DSMEM);

    prep_pack_b<<<Bb, 256>>>(features, b_ih, b_hh, mask);
    prep_v<<<dim3(8, 2), 256>>>(W1, W2, V);
    prep_vred<<<8, 256>>>();
    prep_wfr<<<1536, 256>>>(w_ih, w_hh);

    gru_persist<<<GRID, THREADS, DSMEM>>>(inputs, mask, probs, ctx);
}

// round 17
// speedup vs baseline: 1.3388x; 1.3388x over previous
#include <cuda_runtime.h>
#include <cuda_fp16.h>
#include <cstdint>
#include <math.h>

#define Bb 32
#define Hh 1024
#define Ss 512
#define Tt 32
#define N3 3072
#define NN 6144
#define NGEMM 128        // 64 h-slices x 2 batch-halves
#define GRID 144
#define THREADS 384

// smem layout (GEMM CTAs)
#define SM_B 0            // 32768: B stage (own batch-half, compacted)
#define SM_Y 32768        // 12288: y [kq 4][48][16] f32
#define SM_GX 45056       // 3072: cached gi [48][16]
#define SM_HOLD 48128     // 1024: hold h [16][16]
#define SM_BIAS 49152     // 320: br,bz,bni,bnh,v1 x16
#define SM_C256 49472     // 1024
#define SM_FLG 50496      // 16
#define DSMEM 50688

// ===================== helpers =====================
__device__ __forceinline__ uint32_t smem_u32(const void* p) {
    uint32_t a;
    asm("{ .reg .u64 t; cvta.to.shared.u64 t, %1; cvt.u32.u64 %0, t; }" : "=r"(a) : "l"(p));
    return a;
}
__device__ __forceinline__ uint32_t pack_h2(__half x, __half y) {
    return (uint32_t)__half_as_ushort(x) | ((uint32_t)__half_as_ushort(y) << 16);
}
__device__ __forceinline__ float fsigmoid(float x) { return 1.f / (1.f + __expf(-x)); }
__device__ __forceinline__ float ftanh(float x) { return 2.f / (1.f + __expf(-2.f * x)) - 1.f; }
__device__ __forceinline__ void mma16816(float* c, const uint32_t* a, uint32_t b0, uint32_t b1) {
    asm volatile(
        "mma.sync.aligned.m16n8k16.row.col.f32.f16.f16.f32 "
        "{%0,%1,%2,%3}, {%4,%5,%6,%7}, {%8,%9}, {%0,%1,%2,%3};"
        : "+f"(c[0]), "+f"(c[1]), "+f"(c[2]), "+f"(c[3])
        : "r"(a[0]), "r"(a[1]), "r"(a[2]), "r"(a[3]), "r"(b0), "r"(b1));
}
// B-fragment byte offset for (k=j in [0,1024), n=b in [0,32))
__device__ __forceinline__ uint32_t bx_off(int j, int b) {
    int kc = j >> 4, r = j & 15;
    int nn = b >> 3, g = b & 7, t = (r & 7) >> 1;
    return (uint32_t)(kc * 1024 + nn * 256 + (g * 4 + t) * 8 + ((r >= 8) ? 4 : 0) + (r & 1) * 2);
}
__device__ __forceinline__ unsigned atom_add_acqrel(unsigned* p, unsigned v) {
    unsigned old;
    asm volatile("atom.add.acq_rel.gpu.u32 %0, [%1], %2;" : "=r"(old) : "l"(p), "r"(v) : "memory");
    return old;
}
__device__ __forceinline__ unsigned ld_acquire(unsigned* p) {
    unsigned v;
    asm volatile("ld.acquire.gpu.u32 %0, [%1];" : "=r"(v) : "l"(p) : "memory");
    return v;
}
__device__ __forceinline__ void st_release(unsigned* p, unsigned v) {
    asm volatile("st.release.gpu.u32 [%0], %1;" :: "l"(p), "r"(v) : "memory");
}

// ===================== device scratch =====================
// A fragments: [m 64][wid 12][p 16][lane 32] uint4 (warp wid = gate*4 + kq)
__device__ __align__(128) uint4 g_axh[393216];   // w_ih fp16 hi
__device__ __align__(128) uint4 g_axl[393216];   // w_ih fp16 lo (x4096)
__device__ __align__(128) uint4 g_ahh[393216];   // w_hh fp16 hi
__device__ __align__(128) char g_bx[2][65536];   // B frags fp16 [x|h]
__device__ __align__(16) float g_cp[Tt * 64 * Bb]; // c partials [t][m][b]
__device__ __align__(16) float g_vp[2][8][Hh];
__device__ __align__(16) float g_v1[Hh];
__device__ __align__(16) float g_v2[Hh];
__device__ __align__(16) float g_a[Bb * Ss];
__device__ __align__(16) float g_bias[NN];
__device__ int g_mask_nzv[Bb];
// sync counters: each on its own 128B line (no sector sharing between pollers/atomics)
__device__ __align__(128) unsigned g_hcnt;
__device__ __align__(128) unsigned g_hrel;
__device__ __align__(128) unsigned g_xcnt;
__device__ __align__(128) unsigned g_xrel;
__device__ __align__(128) unsigned g_acnt;
__device__ __align__(128) unsigned g_arel;

// ===================== prep kernels =====================
__global__ void prep_pack_b(const float* __restrict__ features,
                            const float* __restrict__ b_ih,
                            const float* __restrict__ b_hh,
                            const float* __restrict__ mask) {
    int b = blockIdx.x, tid = threadIdx.x;
    int lane = tid & 31, wid = tid >> 5;
    if (b == 0 && tid == 0) {
        g_hcnt = 0u; g_xcnt = 0u; g_acnt = 0u;
        g_hrel = 0u; g_xrel = 0u; g_arel = 0u;
    }
    int bi = b * 256 + tid;
    if (bi < N3) g_bias[bi] = b_ih[bi];
    else if (bi < NN) g_bias[bi] = b_hh[bi - N3];
    __shared__ unsigned wnz[8];
    float m0 = mask[b * Ss + tid], m1 = mask[b * Ss + tid + 256];
    unsigned bal = __ballot_sync(0xFFFFFFFFu, (m0 != 0.f) || (m1 != 0.f));
    if (lane == 0) wnz[wid] = bal;
    __syncthreads();
    if (tid == 0) {
        unsigned o = 0;
#pragma unroll
        for (int i = 0; i < 8; i++) o |= wnz[i];
        g_mask_nzv[b] = (o != 0u);
    }
#pragma unroll
    for (int jj = 0; jj < 4; jj++) {
        int j = tid + jj * 256;
        float v = features[b * Hh + j];
        uint32_t off = bx_off(j, b);
        *(unsigned short*)(g_bx[0] + off) = __half_as_ushort(__float2half_rn(v));
        *(unsigned short*)(g_bx[1] + off) = 0;
    }
}

__global__ void prep_v(const float* __restrict__ W1, const float* __restrict__ W2,
                       const float* __restrict__ V) {
    int hc = blockIdx.x, sel = blockIdx.y, tid = threadIdx.x;
    const float* W = sel ? W2 : W1;
    __shared__ float vs[128];
    if (tid < 128) vs[tid] = V[hc * 128 + tid];
    __syncthreads();
    float acc[4] = {0.f, 0.f, 0.f, 0.f};
    for (int h = 0; h < 128; h++) {
        const float* row = W + (size_t)(hc * 128 + h) * Hh;
        float vh = vs[h];
#pragma unroll
        for (int q = 0; q < 4; q++) acc[q] = fmaf(vh, row[tid + q * 256], acc[q]);
    }
#pragma unroll
    for (int q = 0; q < 4; q++) g_vp[sel][hc][tid + q * 256] = acc[q];
}

__global__ void prep_vred() {
    int i = blockIdx.x * 256 + threadIdx.x;
    int sel = i >> 10, d = i & 1023;
    float s = 0.f;
#pragma unroll
    for (int hc = 0; hc < 8; hc++) s += g_vp[sel][hc][d];
    if (sel) g_v2[d] = s; else g_v1[d] = s;
}

// pack W rows: slice m, warp (wm,kq) -> gate wm, rows m*16+jl, K-quarter kq
__global__ void prep_wfr(const float* __restrict__ w_ih, const float* __restrict__ w_hh) {
    int idx = blockIdx.x * 256 + threadIdx.x;   // 393216
    int lane = idx & 31;
    int p = (idx >> 5) & 15;
    int rest = idx >> 9;                         // 0..767
    int wid = rest % 12;
    int m = rest / 12;
    int wm = wid >> 2, kq = wid & 3;
    int gq = lane >> 2, tq = lane & 3;
    int k0 = kq * 256 + p * 16 + 2 * tq;

    int jl[2] = {gq, gq + 8};
    float vx[8], vh4[8];
#pragma unroll
    for (int rr = 0; rr < 2; rr++) {
        int Wrow = wm * 1024 + m * 16 + jl[rr];
        const float* Xr = w_ih + (size_t)Wrow * Hh;
        const float* Hr = w_hh + (size_t)Wrow * Hh;
        vx[rr * 2 + 0] = Xr[k0];     vx[rr * 2 + 1] = Xr[k0 + 1];
        vx[rr * 2 + 4] = Xr[k0 + 8]; vx[rr * 2 + 5] = Xr[k0 + 9];
        vh4[rr * 2 + 0] = Hr[k0];     vh4[rr * 2 + 1] = Hr[k0 + 1];
        vh4[rr * 2 + 4] = Hr[k0 + 8]; vh4[rr * 2 + 5] = Hr[k0 + 9];
    }
    uint32_t xh[4], xl[4], hh[4];
#pragma unroll
    for (int i = 0; i < 4; i++) {
        float a = vx[2 * i], b = vx[2 * i + 1];
        __half ha = __float2half_rn(a), hb = __float2half_rn(b);
        __half la = __float2half_rn((a - __half2float(ha)) * 4096.f);
        __half lb = __float2half_rn((b - __half2float(hb)) * 4096.f);
        xh[i] = pack_h2(ha, hb);
        xl[i] = pack_h2(la, lb);
        hh[i] = pack_h2(__float2half_rn(vh4[2 * i]), __float2half_rn(vh4[2 * i + 1]));
    }
    g_axh[idx] = make_uint4(xh[0], xh[1], xh[2], xh[3]);
    g_axl[idx] = make_uint4(xl[0], xl[1], xl[2], xl[3]);
    g_ahh[idx] = make_uint4(hh[0], hh[1], hh[2], hh[3]);
}

// ===================== persistent kernel =====================
extern __shared__ char dsm[];

// stage own batch-half columns (32KB compacted: 64 kc x 512B)
__device__ __forceinline__ void stageB(const char* __restrict__ src, int bh, int tid) {
    uint32_t sb = smem_u32(dsm);
    for (int i = tid; i < 2048; i += THREADS) {
        int kc = i >> 5, ch = i & 31;
        asm volatile("cp.async.cg.shared.global [%0], [%1], 16;"
            :: "r"(sb + i * 16),
               "l"(__cvta_generic_to_global(src + kc * 1024 + bh * 512 + ch * 16)) : "memory");
    }
    asm volatile("cp.async.commit_group;" ::: "memory");
    asm volatile("cp.async.wait_group 0;" ::: "memory");
    __syncthreads();
}

__global__ void __launch_bounds__(THREADS, 1)
gru_persist(const float* __restrict__ inputs, const float* __restrict__ mask,
            float* __restrict__ probs, float* __restrict__ ctx) {
    const int c = blockIdx.x;            // 0..143
    const int tid = threadIdx.x;
    const int wid = tid >> 5;
    const int lane = tid & 31;

    // ======= phase 0: grid-wide a-compute (a[b,s] = inputs[b,s,:].v2) =======
    {
        float* v2s = (float*)dsm;
        for (int i = tid; i < Hh; i += THREADS) v2s[i] = g_v2[i];
        __syncthreads();
        int gw = c * 12 + wid;                 // 0..1727
        for (int row = gw; row < Bb * Ss; row += GRID * 12) {
            const float* r = inputs + (size_t)row * Hh;
            float acc = 0.f;
#pragma unroll
            for (int i = 0; i < 8; i++) {
                float4 x4 = *(const float4*)&r[(i * 32 + lane) * 4];
                float4 v4 = *(const float4*)&v2s[(i * 32 + lane) * 4];
                acc += x4.x * v4.x + x4.y * v4.y + x4.z * v4.z + x4.w * v4.w;
            }
#pragma unroll
            for (int o = 16; o > 0; o >>= 1) acc += __shfl_xor_sync(0xFFFFFFFFu, acc, o);
            if (lane == 0) g_a[row] = acc;
        }
        __syncthreads();
        if (tid == 0) {
            unsigned prev = atom_add_acqrel(&g_acnt, 1u);
            if (prev == (unsigned)(GRID - 1)) st_release(&g_arel, 1u);
        }
        __syncthreads();
    }

    // ================= scorer CTAs (2 batches each) =================
    if (c >= NGEMM) {
        const int pb = (c - NGEMM) * 2;  // first batch of the pair
        float* p   = (float*)(dsm + 8192);      // 512 f
        float* red2 = (float*)(dsm + 10240);
        int*   si2  = (int*)(dsm + 10496);
        int*   sfl  = (int*)(dsm + 10752);

        if (tid == 0) {
            int nz = 0;
#pragma unroll
            for (int i = 0; i < Bb; i++) nz |= g_mask_nzv[i];
            sfl[0] = nz;
        }
        // wait for a (written by all CTAs)
        if (tid == 0) { while (ld_acquire(&g_arel) == 0u) { } }
        __syncthreads();
        const bool mask_nz = (sfl[0] != 0);

        float aA0 = 0.f, aA1 = 0.f, aB0 = 0.f, aB1 = 0.f;
        if (tid < 256) {
            aA0 = g_a[pb * Ss + tid];
            aA1 = g_a[pb * Ss + tid + 256];
            aB0 = g_a[(pb + 1) * Ss + tid];
            aB1 = g_a[(pb + 1) * Ss + tid + 256];
        }

        for (int t = 0; t < Tt; t++) {
            if (tid == 0) { while (ld_acquire(&g_hrel) < (unsigned)(t + 1)) { } }
            __syncthreads();
            // c for both batches in parallel: tid<128
            if (tid < 128) {
                int bi = tid >> 6, idx = tid & 63;
                float v = g_cp[(t * 64 + idx) * Bb + pb + bi];
#pragma unroll
                for (int o = 16; o > 0; o >>= 1) v += __shfl_xor_sync(0xFFFFFFFFu, v, o);
                if (lane == 0) red2[wid] = v;
            }
            __syncthreads();
            const float cA = red2[0] + red2[1];
            const float cB = red2[2] + red2[3];
#pragma unroll
            for (int bi = 0; bi < 2; bi++) {
                const int b2 = pb + bi;
                const float c0v = bi ? cB : cA;
                float s0 = 0.f, s1 = 0.f;
                if (tid < 256) {
                    s0 = ftanh(c0v + (bi ? aB0 : aA0));
                    s1 = ftanh(c0v + (bi ? aB1 : aA1));
                    float* pr = probs + ((size_t)b2 * Tt + t) * Ss;
                    pr[tid] = s0;
                    pr[tid + 256] = s1;
                }
                if (t == 0 || mask_nz) {
                    if (tid < 256) {
                        float m0 = s0 + mask[b2 * Ss + tid];
                        float m1 = s1 + mask[b2 * Ss + tid + 256];
                        float bv = m0; int bi2 = tid;
                        if (m1 > bv) { bv = m1; bi2 = tid + 256; }
#pragma unroll
                        for (int o = 16; o > 0; o >>= 1) {
                            float v = __shfl_xor_sync(0xFFFFFFFFu, bv, o);
                            int ii = __shfl_xor_sync(0xFFFFFFFFu, bi2, o);
                            if (v > bv || (v == bv && ii < bi2)) { bv = v; bi2 = ii; }
                        }
                        if (lane == 0) { red2[8 + wid] = bv; si2[wid] = bi2; }
                    }
                    __syncthreads();
                    if (tid == 0) {
                        float v = red2[8]; int ii = si2[0];
#pragma unroll
                        for (int i = 1; i < 8; i++) {
                            float v2 = red2[8 + i]; int i2 = si2[i];
                            if (v2 > v || (v2 == v && i2 < ii)) { v = v2; ii = i2; }
                        }
                        si2[15] = ii;
                    }
                    __syncthreads();
                    int idx = si2[15];
                    const float* xr = inputs + ((size_t)b2 * Ss + idx) * Hh;
                    for (int k2 = tid; k2 < Hh; k2 += THREADS) {
                        *(unsigned short*)(g_bx[0] + bx_off(k2, b2)) =
                            __half_as_ushort(__float2half_rn(xr[k2]));
                    }
                    __syncthreads();
                }
            }
            if (t == 0 || mask_nz) {
                if (tid == 0) {
                    unsigned prev = atom_add_acqrel(&g_xcnt, 1u);
                    if ((prev & 15u) == 15u) st_release(&g_xrel, (unsigned)(t + 1));
                }
            }
            if (t == 0) {
                // ctx for both batches (overlapped with remaining steps)
#pragma unroll
                for (int bi = 0; bi < 2; bi++) {
                    const int b2 = pb + bi;
                    for (int s = tid; s < Ss; s += THREADS)
                        p[s] = probs[(size_t)b2 * Tt * Ss + s] + mask[b2 * Ss + s];
                    __syncthreads();
                    if (tid < 256) {
                        float m = fmaxf(p[tid], p[tid + 256]);
#pragma unroll
                        for (int o = 16; o > 0; o >>= 1) m = fmaxf(m, __shfl_xor_sync(0xFFFFFFFFu, m, o));
                        if (lane == 0) red2[16 + wid] = m;
                    }
                    __syncthreads();
                    if (tid == 0) {
                        float mm = red2[16];
#pragma unroll
                        for (int i = 1; i < 8; i++) mm = fmaxf(mm, red2[16 + i]);
                        red2[24] = mm;
                    }
                    __syncthreads();
                    const float mx = red2[24];
                    float sm = 0.f;
                    if (tid < 256) {
                        float e0 = __expf(p[tid] - mx), e1 = __expf(p[tid + 256] - mx);
                        p[tid] = e0; p[tid + 256] = e1;
                        sm = e0 + e1;
#pragma unroll
                        for (int o = 16; o > 0; o >>= 1) sm += __shfl_xor_sync(0xFFFFFFFFu, sm, o);
                        if (lane == 0) red2[32 + wid] = sm;
                    }
                    __syncthreads();
                    if (tid == 0) {
                        float ss = 0.f;
#pragma unroll
                        for (int i = 0; i < 8; i++) ss += red2[32 + i];
                        red2[40] = ss;
                    }
                    __syncthreads();
                    const float Z = red2[40];
                    if (tid < 256) {
                        float acc[4] = {0.f, 0.f, 0.f, 0.f};
                        for (int s = 0; s < Ss; s++) {
                            const float* row = inputs + ((size_t)b2 * Ss + s) * Hh;
                            float ps = p[s];
#pragma unroll
                            for (int q = 0; q < 4; q++) acc[q] = fmaf(ps, row[tid + q * 256], acc[q]);
                        }
#pragma unroll
                        for (int q = 0; q < 4; q++) ctx[b2 * Hh + tid + q * 256] = acc[q] / Z;
                    }
                    __syncthreads();
                }
            }
        }
        return;
    }

    // ================= GEMM + fused-update CTAs =================
    const int m = c >> 1;                // h-slice 0..63
    const int bh = c & 1;                // batch half
    const int kq = wid & 3;              // K-quarter

    float* yq   = (float*)(dsm + SM_Y);          // [kq][48][16]
    float* gxs  = (float*)(dsm + SM_GX);         // [48][16]
    float* hold = (float*)(dsm + SM_HOLD);       // [16][16]
    float* brS  = (float*)(dsm + SM_BIAS);
    float* bzS  = brS + 16;
    float* bniS = brS + 32;
    float* bnhS = brS + 48;
    float* v1S  = brS + 64;
    float* c256 = (float*)(dsm + SM_C256);
    int*   sfl  = (int*)(dsm + SM_FLG);

    if (tid == 0) {
        int nz = 0;
#pragma unroll
        for (int i = 0; i < Bb; i++) nz |= g_mask_nzv[i];
        sfl[0] = nz;
    }
    if (tid < 16) {
        int jg = m * 16 + tid;
        brS[tid] = g_bias[jg] + g_bias[3072 + jg];
        bzS[tid] = g_bias[1024 + jg] + g_bias[4096 + jg];
        bniS[tid] = g_bias[2048 + jg];
        bnhS[tid] = g_bias[5120 + jg];
        v1S[tid] = g_v1[jg];
    }
    for (int i = tid; i < 256; i += THREADS) hold[i] = 0.f;
    __syncthreads();
    const bool mask_nz = (sfl[0] != 0);

    const size_t abase = ((size_t)(m * 12 + wid)) * 512;   // [m][wid][p][lane]
    const uint4* Axh = g_axh + abase;
    const uint4* Axl = g_axl + abase;
    const uint4* Ahh = g_ahh + abase;

    // ---- steady-state h-weights live in registers (loaded once) ----
    uint4 AHH[16];
#pragma unroll
    for (int p = 0; p < 16; p++) AHH[p] = Ahh[p * 32 + lane];

    float* ybW = yq + kq * 768;          // this K-quarter's buffer [48][16]
    const int wm = wid >> 2;
    const int r0 = wm * 16 + (lane >> 2);
    const int c0f = 2 * (lane & 3);

    for (int t = 0; t < Tt; t++) {
        const bool xp = (t <= 1) || mask_nz;
        const bool hp = (t >= 1);
        if (t >= 1) {
            if (tid == 0) {
                while (ld_acquire(&g_hrel) < (unsigned)t) { }
                if (xp) { while (ld_acquire(&g_xrel) < (unsigned)t) { } }
            }
            __syncthreads();
        }

        if (xp) {
            stageB(g_bx[0], bh, tid);
            float acch[2][4], accl[2][4];
#pragma unroll
            for (int i = 0; i < 2; i++)
#pragma unroll
                for (int j = 0; j < 4; j++) { acch[i][j] = 0.f; accl[i][j] = 0.f; }
            uint4 AH[4], AL[4];
#pragma unroll
            for (int p = 0; p < 3; p++) { AH[p] = Axh[p * 32 + lane]; AL[p] = Axl[p * 32 + lane]; }
#pragma unroll
            for (int p = 0; p < 16; p++) {
                const int s = p & 3;
                if (p + 3 < 16) {
                    const int q = (p + 3) & 3;
                    AH[q] = Axh[(p + 3) * 32 + lane];
                    AL[q] = Axl[(p + 3) * 32 + lane];
                }
                const char* bb = dsm + (kq * 16 + p) * 512 + lane * 8;
#pragma unroll
                for (int nn = 0; nn < 2; nn++) {
                    uint2 bv = *(const uint2*)(bb + nn * 256);
                    mma16816(acch[nn], &AH[s].x, bv.x, bv.y);
                    mma16816(accl[nn], &AL[s].x, bv.x, bv.y);
                }
            }
#pragma unroll
            for (int nn = 0; nn < 2; nn++) {
                int col = nn * 8 + c0f;
                ybW[r0 * 16 + col]           = acch[nn][0] + accl[nn][0] * (1.f / 4096.f);
                ybW[r0 * 16 + col + 1]       = acch[nn][1] + accl[nn][1] * (1.f / 4096.f);
                ybW[(r0 + 8) * 16 + col]     = acch[nn][2] + accl[nn][2] * (1.f / 4096.f);
                ybW[(r0 + 8) * 16 + col + 1] = acch[nn][3] + accl[nn][3] * (1.f / 4096.f);
            }
            __syncthreads();
            for (int i = tid; i < 768; i += THREADS)
                gxs[i] = yq[i] + yq[768 + i] + yq[1536 + i] + yq[2304 + i];
            __syncthreads();
        }

        if (hp) {
            stageB(g_bx[1], bh, tid);
            float acch[2][4];
#pragma unroll
            for (int i = 0; i < 2; i++)
#pragma unroll
                for (int j = 0; j < 4; j++) acch[i][j] = 0.f;
#pragma unroll
            for (int p = 0; p < 16; p++) {
                const char* bb = dsm + (kq * 16 + p) * 512 + lane * 8;
#pragma unroll
                for (int nn = 0; nn < 2; nn++) {
                    uint2 bv = *(const uint2*)(bb + nn * 256);
                    mma16816(acch[nn], &AHH[p].x, bv.x, bv.y);
                }
            }
#pragma unroll
            for (int nn = 0; nn < 2; nn++) {
                int col = nn * 8 + c0f;
                ybW[r0 * 16 + col]           = acch[nn][0];
                ybW[r0 * 16 + col + 1]       = acch[nn][1];
                ybW[(r0 + 8) * 16 + col]     = acch[nn][2];
                ybW[(r0 + 8) * 16 + col + 1] = acch[nn][3];
            }
            __syncthreads();
        }

        // ---- fused GRU update for h[m*16..+16) x batches[bh*16..+16) ----
        if (tid < 256) {
            int jl = tid >> 4, bl = tid & 15;
            float yr = 0.f, yz = 0.f, yn = 0.f;
            if (hp) {
                yr = yq[jl * 16 + bl]        + yq[768 + jl * 16 + bl]
                   + yq[1536 + jl * 16 + bl] + yq[2304 + jl * 16 + bl];
                yz = yq[(16 + jl) * 16 + bl]        + yq[768 + (16 + jl) * 16 + bl]
                   + yq[1536 + (16 + jl) * 16 + bl] + yq[2304 + (16 + jl) * 16 + bl];
                yn = yq[(32 + jl) * 16 + bl]        + yq[768 + (32 + jl) * 16 + bl]
                   + yq[1536 + (32 + jl) * 16 + bl] + yq[2304 + (32 + jl) * 16 + bl];
            }
            float r = fsigmoid(gxs[jl * 16 + bl] + yr + brS[jl]);
            float z = fsigmoid(gxs[(16 + jl) * 16 + bl] + yz + bzS[jl]);
            float nv = ftanh(gxs[(32 + jl) * 16 + bl] + bniS[jl] + r * (yn + bnhS[jl]));
            float hnew = (1.f - z) * nv + z * hold[tid];
            hold[tid] = hnew;
            *(unsigned short*)(g_bx[1] + bx_off(m * 16 + jl, bh * 16 + bl)) =
                __half_as_ushort(__float2half_rn(hnew));
            c256[tid] = v1S[jl] * hnew;
        }
        __syncthreads();
        if (tid < 16) {
            float s = 0.f;
#pragma unroll
            for (int jl = 0; jl < 16; jl++) s += c256[jl * 16 + tid];
            g_cp[(t * 64 + m) * Bb + bh * 16 + tid] = s;
        }
        __syncthreads();
        if (tid == 0) {
            unsigned prev = atom_add_acqrel(&g_hcnt, 1u);
            if ((prev & 127u) == 127u) st_release(&g_hrel, (unsigned)(t + 1));
        }
    }
}

// ===================== launch =====================
extern "C" void kernel_launch(void* const* d_in, const int* in_sizes, int n_in,
                              void* d_out, int out_size) {
    const float* inputs   = (const float*)d_in[0];
    const float* mask     = (const float*)d_in[1];
    // d_in[2] = inputs_embeds (unused, use_emb=False)
    const float* features = (const float*)d_in[3];
    const float* w_ih     = (const float*)d_in[4];
    const float* b_ih     = (const float*)d_in[5];
    const float* w_hh     = (const float*)d_in[6];
    const float* b_hh     = (const float*)d_in[7];
    const float* W1       = (const float*)d_in[8];
    const float* W2       = (const float*)d_in[9];
    const float* V        = (const float*)d_in[10];

    float* out   = (float*)d_out;
    float* probs = out;                            // [B, T, S]
    float* ctx   = out + (size_t)Bb * Tt * Ss;     // [B, H]

    cudaFuncSetAttribute(gru_persist, cudaFuncAttributeMaxDynamicSharedMemorySize, DSMEM);

    prep_pack_b<<<Bb, 256>>>(features, b_ih, b_hh, mask);
    prep_v<<<dim3(8, 2), 256>>>(W1, W2, V);
    prep_vred<<<8, 256>>>();
    prep_wfr<<<1536, 256>>>(w_ih, w_hh);

    gru_persist<<<GRID, THREADS, DSMEM>>>(inputs, mask, probs, ctx);
}